// round 2
// baseline (speedup 1.0000x reference)
#include <cuda_runtime.h>

// ---------------------------------------------------------------------------
// DLRM small — fp32 baseline
//   dense[B,13] -> bottom MLP (13->512->256->128, relu)
//   emb gather [B,26,128]; combined = [h | emb] -> Gram 27x27 -> triu 378
//   top_in = [h(128) | triu(378)] = 506 -> top MLP (506->1024->1024->512->256->1)
// Inputs (metadata order):
//   0 dense f32[65536,13]   1 sparse_idx i32[65536,26]  2 emb f32[1048576,128]
//   3 bw0[13,512] 4 bb0[512] 5 bw1[512,256] 6 bb1[256] 7 bw2[256,128] 8 bb2[128]
//   9 tw0[506,1024] 10 tb0[1024] 11 tw1[1024,1024] 12 tb1[1024]
//  13 tw2[1024,512] 14 tb2[512] 15 tw3[512,256] 16 tb3[256] 17 tw4[256,1] 18 tb4[1]
// Output: f32[65536]
// ---------------------------------------------------------------------------

#define BATCH 65536
#define VOCAB_MASK 0xFFFFF   // VOCAB = 2^20

constexpr int BM = 128, BN = 128, BK = 8, TM = 8, TN = 8;

// Scratch (allocation-free rule: static device globals)
__device__ float g_bufA[(size_t)BATCH * 1024];
__device__ float g_bufB[(size_t)BATCH * 1024];
__device__ float g_h[(size_t)BATCH * 128];

// ---------------------------------------------------------------------------
// Generic tiled SGEMM: C[M,N] = act(A[M,K] @ W[K,N] + bias)
// M = 65536 (multiple of 128), N in {128,256,512,1024} (multiple of 128).
// Only K needs bounds handling (13, 506).
// ---------------------------------------------------------------------------
__global__ __launch_bounds__(256) void sgemm_kernel(
    const float* __restrict__ A, const float* __restrict__ W,
    const float* __restrict__ bias, float* __restrict__ C,
    int K, int N, int lda, int ldc, int doRelu)
{
    __shared__ float As[BK][BM];
    __shared__ float Bs[BK][BN];
    const int tid = threadIdx.x;
    const int tn = tid & 15;          // 0..15 -> col group
    const int tm = tid >> 4;          // 0..15 -> row group
    const int m0 = blockIdx.y * BM;
    const int n0 = blockIdx.x * BN;
    const float* Ab = A + (size_t)m0 * lda;
    const float* Wb = W + n0;

    float acc[TM][TN];
#pragma unroll
    for (int i = 0; i < TM; i++)
#pragma unroll
        for (int j = 0; j < TN; j++) acc[i][j] = 0.f;

    // load mappings
    const int arow = tid >> 1;        // 0..127
    const int ak   = (tid & 1) * 4;   // 0 or 4
    const int bk   = tid >> 5;        // 0..7
    const int bn   = (tid & 31) * 4;  // 0..124

    for (int k0 = 0; k0 < K; k0 += BK) {
#pragma unroll
        for (int i = 0; i < 4; i++) {
            int k = k0 + ak + i;
            As[ak + i][arow] = (k < K) ? Ab[(size_t)arow * lda + k] : 0.f;
        }
        {
            int k = k0 + bk;
            float4 v = make_float4(0.f, 0.f, 0.f, 0.f);
            if (k < K) v = *reinterpret_cast<const float4*>(Wb + (size_t)k * N + bn);
            *reinterpret_cast<float4*>(&Bs[bk][bn]) = v;
        }
        __syncthreads();
#pragma unroll
        for (int kk = 0; kk < BK; kk++) {
            float4 a0 = *reinterpret_cast<const float4*>(&As[kk][tm * TM]);
            float4 a1 = *reinterpret_cast<const float4*>(&As[kk][tm * TM + 4]);
            float4 b0 = *reinterpret_cast<const float4*>(&Bs[kk][tn * TN]);
            float4 b1 = *reinterpret_cast<const float4*>(&Bs[kk][tn * TN + 4]);
            float a[8] = {a0.x, a0.y, a0.z, a0.w, a1.x, a1.y, a1.z, a1.w};
            float b[8] = {b0.x, b0.y, b0.z, b0.w, b1.x, b1.y, b1.z, b1.w};
#pragma unroll
            for (int i = 0; i < TM; i++)
#pragma unroll
                for (int j = 0; j < TN; j++)
                    acc[i][j] = fmaf(a[i], b[j], acc[i][j]);
        }
        __syncthreads();
    }

#pragma unroll
    for (int i = 0; i < TM; i++) {
        size_t row = (size_t)m0 + tm * TM + i;
#pragma unroll
        for (int j = 0; j < TN; j += 4) {
            int col = n0 + tn * TN + j;
            float4 v;
            v.x = acc[i][j + 0] + bias[col + 0];
            v.y = acc[i][j + 1] + bias[col + 1];
            v.z = acc[i][j + 2] + bias[col + 2];
            v.w = acc[i][j + 3] + bias[col + 3];
            if (doRelu) {
                v.x = fmaxf(v.x, 0.f); v.y = fmaxf(v.y, 0.f);
                v.z = fmaxf(v.z, 0.f); v.w = fmaxf(v.w, 0.f);
            }
            *reinterpret_cast<float4*>(&C[row * ldc + col]) = v;
        }
    }
}

// ---------------------------------------------------------------------------
// Embedding gather + pairwise interaction + concat.
// One block (128 threads) per batch row. out row stride = 512 (506 used).
// ---------------------------------------------------------------------------
__global__ __launch_bounds__(128) void interact_kernel(
    const float* __restrict__ h, const int* __restrict__ sidx,
    const float* __restrict__ emb, float* __restrict__ out)
{
    __shared__ float comb[27][129];   // pad 129: conflict-free across rows
    const int row = blockIdx.x;
    const int t = threadIdx.x;        // 0..127

    float hv = h[(size_t)row * 128 + t];
    comb[0][t] = hv;
    const int* si = sidx + (size_t)row * 26;
#pragma unroll
    for (int j = 0; j < 26; j++) {
        unsigned e = ((unsigned)si[j]) & VOCAB_MASK;
        comb[j + 1][t] = emb[(size_t)e * 128 + t];
    }
    __syncthreads();

    float* orow = out + (size_t)row * 512;
    orow[t] = hv;                                  // first 128 = h

    for (int p = t; p < 378; p += 128) {
        int r = 0, rem = p;
        while (rem >= 27 - r) { rem -= 27 - r; r++; }
        int c = r + rem;
        float s = 0.f;
#pragma unroll 8
        for (int d = 0; d < 128; d++)
            s = fmaf(comb[r][d], comb[c][d], s);
        orow[128 + p] = s;                         // triu, row-major order
    }
}

// ---------------------------------------------------------------------------
// Final layer: out[B] = A[B,256] @ w[256] + b. One warp per row.
// ---------------------------------------------------------------------------
__global__ __launch_bounds__(256) void final_kernel(
    const float* __restrict__ A, const float* __restrict__ w,
    const float* __restrict__ bias, float* __restrict__ out)
{
    int warp = (blockIdx.x * blockDim.x + threadIdx.x) >> 5;
    int lane = threadIdx.x & 31;
    const float* a = A + (size_t)warp * 256;
    float s = 0.f;
#pragma unroll
    for (int i = 0; i < 8; i++)
        s = fmaf(a[lane + i * 32], __ldg(&w[lane + i * 32]), s);
#pragma unroll
    for (int o = 16; o; o >>= 1) s += __shfl_xor_sync(0xFFFFFFFFu, s, o);
    if (lane == 0) out[warp] = s + bias[0];
}

// ---------------------------------------------------------------------------
extern "C" void kernel_launch(void* const* d_in, const int* in_sizes, int n_in,
                              void* d_out, int out_size)
{
    const float* dense = (const float*)d_in[0];
    const int*   sidx  = (const int*)d_in[1];
    const float* emb   = (const float*)d_in[2];
    const float* bw0 = (const float*)d_in[3];  const float* bb0 = (const float*)d_in[4];
    const float* bw1 = (const float*)d_in[5];  const float* bb1 = (const float*)d_in[6];
    const float* bw2 = (const float*)d_in[7];  const float* bb2 = (const float*)d_in[8];
    const float* tw0 = (const float*)d_in[9];  const float* tb0 = (const float*)d_in[10];
    const float* tw1 = (const float*)d_in[11]; const float* tb1 = (const float*)d_in[12];
    const float* tw2 = (const float*)d_in[13]; const float* tb2 = (const float*)d_in[14];
    const float* tw3 = (const float*)d_in[15]; const float* tb3 = (const float*)d_in[16];
    const float* tw4 = (const float*)d_in[17]; const float* tb4 = (const float*)d_in[18];
    float* out = (float*)d_out;

    float *bufA = nullptr, *bufB = nullptr, *hbuf = nullptr;
    cudaGetSymbolAddress((void**)&bufA, g_bufA);
    cudaGetSymbolAddress((void**)&bufB, g_bufB);
    cudaGetSymbolAddress((void**)&hbuf, g_h);

    dim3 blk(256);
    auto grid = [](int N) { return dim3(N / BN, BATCH / BM); };

    // bottom MLP
    sgemm_kernel<<<grid(512),  blk>>>(dense, bw0, bb0, bufA, 13,  512,  13,  512, 1);
    sgemm_kernel<<<grid(256),  blk>>>(bufA,  bw1, bb1, bufB, 512, 256,  512, 256, 1);
    sgemm_kernel<<<grid(128),  blk>>>(bufB,  bw2, bb2, hbuf, 256, 128,  256, 128, 1);

    // gather + interaction + concat -> bufA rows of 512 (506 valid)
    interact_kernel<<<BATCH, 128>>>(hbuf, sidx, emb, bufA);

    // top MLP
    sgemm_kernel<<<grid(1024), blk>>>(bufA, tw0, tb0, bufB, 506,  1024, 512,  1024, 1);
    sgemm_kernel<<<grid(1024), blk>>>(bufB, tw1, tb1, bufA, 1024, 1024, 1024, 1024, 1);
    sgemm_kernel<<<grid(512),  blk>>>(bufA, tw2, tb2, bufB, 1024, 512,  1024, 512,  1);
    sgemm_kernel<<<grid(256),  blk>>>(bufB, tw3, tb3, bufA, 512,  256,  512,  256,  1);

    // final 256 -> 1
    final_kernel<<<BATCH * 32 / 256, blk>>>(bufA, tw4, tb4, out);
}

// round 3
// speedup vs baseline: 1.9836x; 1.9836x over previous
#include <cuda_runtime.h>
#include <cuda_bf16.h>
#include <cstdint>

// ---------------------------------------------------------------------------
// DLRM small — bf16 split-precision tensor-core version
// Every GEMM: A,W split into bf16 (hi, lo) planes; 3 MMA passes
//   acc += Ahi*Whi + Alo*Whi + Ahi*Wlo   (fp32 accum, ~1e-5 rel err)
// Activations stored as bf16 hi/lo planes between layers.
// ---------------------------------------------------------------------------

#define BATCH 65536
#define VOCAB_MASK 0xFFFFFu

// ---------------- scratch (allocation-free rule) ----------------
__device__ __nv_bfloat16 g_p_hi[(size_t)BATCH * 1024];
__device__ __nv_bfloat16 g_p_lo[(size_t)BATCH * 1024];
__device__ __nv_bfloat16 g_q_hi[(size_t)BATCH * 1024];
__device__ __nv_bfloat16 g_q_lo[(size_t)BATCH * 1024];
__device__ __nv_bfloat16 g_h_hi[(size_t)BATCH * 128];
__device__ __nv_bfloat16 g_h_lo[(size_t)BATCH * 128];
// weight planes, all layers concatenated (2,408,448 elems)
__device__ __nv_bfloat16 g_w_hi[2408448];
__device__ __nv_bfloat16 g_w_lo[2408448];

// ---------------- helpers ----------------
__device__ __forceinline__ void split2(float x, __nv_bfloat16& h, __nv_bfloat16& l) {
    h = __float2bfloat16(x);
    l = __float2bfloat16(x - __bfloat162float(h));
}

__device__ __forceinline__ void cp16(uint32_t dst, const void* src) {
    asm volatile("cp.async.cg.shared.global [%0], [%1], 16;\n" :: "r"(dst), "l"(src));
}
__device__ __forceinline__ void cp_commit() { asm volatile("cp.async.commit_group;\n"); }
__device__ __forceinline__ void cp_wait0()  { asm volatile("cp.async.wait_group 0;\n"); }
__device__ __forceinline__ void cp_wait1()  { asm volatile("cp.async.wait_group 1;\n"); }

__device__ __forceinline__ void ldsm4(uint32_t* r, uint32_t addr) {
    asm volatile("ldmatrix.sync.aligned.m8n8.x4.shared.b16 {%0,%1,%2,%3}, [%4];\n"
        : "=r"(r[0]), "=r"(r[1]), "=r"(r[2]), "=r"(r[3]) : "r"(addr));
}
__device__ __forceinline__ void ldsm4t(uint32_t& r0, uint32_t& r1, uint32_t& r2, uint32_t& r3, uint32_t addr) {
    asm volatile("ldmatrix.sync.aligned.m8n8.x4.trans.shared.b16 {%0,%1,%2,%3}, [%4];\n"
        : "=r"(r0), "=r"(r1), "=r"(r2), "=r"(r3) : "r"(addr));
}
__device__ __forceinline__ void mma16816(float* d, const uint32_t* a, const uint32_t* b) {
    asm volatile(
        "mma.sync.aligned.m16n8k16.row.col.f32.bf16.bf16.f32 "
        "{%0,%1,%2,%3}, {%4,%5,%6,%7}, {%8,%9}, {%0,%1,%2,%3};\n"
        : "+f"(d[0]), "+f"(d[1]), "+f"(d[2]), "+f"(d[3])
        : "r"(a[0]), "r"(a[1]), "r"(a[2]), "r"(a[3]), "r"(b[0]), "r"(b[1]));
}

// ---------------- smem layout constants (bf16 element offsets) ----------------
// per stage: A_hi[128][40], A_lo[128][40], W_hi[32][136], W_lo[32][136]
constexpr int SM_A_HI = 0;
constexpr int SM_A_LO = 5120;
constexpr int SM_W_HI = 10240;
constexpr int SM_W_LO = 14592;
constexpr int SM_STAGE = 18944;              // elems
constexpr int SMEM_BYTES = SM_STAGE * 2 * 2; // 75776

// ---------------------------------------------------------------------------
// Split-bf16 GEMM: C[M,N] = relu(A@W + bias), M=65536, N mult of 128,
// K mult of 32 (padded). Emits C as hi/lo bf16 planes.
// ---------------------------------------------------------------------------
__global__ __launch_bounds__(256, 1) void gemm_bf16s(
    const __nv_bfloat16* __restrict__ Ahi, const __nv_bfloat16* __restrict__ Alo,
    const __nv_bfloat16* __restrict__ Whi, const __nv_bfloat16* __restrict__ Wlo,
    const float* __restrict__ bias,
    __nv_bfloat16* __restrict__ Chi, __nv_bfloat16* __restrict__ Clo,
    int K, int N, int lda, int ldc)
{
    extern __shared__ __align__(16) char smem_raw[];
    const uint32_t smem = (uint32_t)__cvta_generic_to_shared(smem_raw);

    const int tid = threadIdx.x;
    const int warp = tid >> 5, lane = tid & 31;
    const int wm = (warp >> 2) * 64;   // warp m-offset in tile
    const int wn = (warp & 3) * 32;    // warp n-offset
    const int m0 = blockIdx.y * 128;
    const int n0 = blockIdx.x * 128;

    const int nk = K >> 5;             // 32-wide K chunks

    auto load_stage = [&](int k0, int st) {
        const uint32_t sbase = smem + st * SM_STAGE * 2;
#pragma unroll
        for (int r = 0; r < 2; r++) {
            int q = tid + r * 256;              // 0..511 : A chunks
            int row = q >> 2, cseg = (q & 3) << 3;
            size_t goff = (size_t)(m0 + row) * lda + k0 + cseg;
            uint32_t soff = (row * 40 + cseg) * 2;
            cp16(sbase + SM_A_HI * 2 + soff, Ahi + goff);
            cp16(sbase + SM_A_LO * 2 + soff, Alo + goff);
        }
#pragma unroll
        for (int r = 0; r < 2; r++) {
            int q = tid + r * 256;              // 0..511 : W chunks
            int row = q >> 4, cseg = (q & 15) << 3;
            size_t goff = (size_t)(k0 + row) * N + n0 + cseg;
            uint32_t soff = (row * 136 + cseg) * 2;
            cp16(sbase + SM_W_HI * 2 + soff, Whi + goff);
            cp16(sbase + SM_W_LO * 2 + soff, Wlo + goff);
        }
    };

    float acc[4][4][4];
#pragma unroll
    for (int i = 0; i < 4; i++)
#pragma unroll
        for (int j = 0; j < 4; j++)
#pragma unroll
            for (int r = 0; r < 4; r++) acc[i][j][r] = 0.f;

    auto compute_stage = [&](int st) {
        const uint32_t sbase = smem + st * SM_STAGE * 2;
#pragma unroll
        for (int kk = 0; kk < 2; kk++) {
            uint32_t ah[4][4], al[4][4], bh[4][2], bl[4][2];
#pragma unroll
            for (int mi = 0; mi < 4; mi++) {
                uint32_t arow = wm + mi * 16 + (lane & 15);
                uint32_t acol = kk * 16 + ((lane >> 4) << 3);
                uint32_t off = (arow * 40 + acol) * 2;
                ldsm4(ah[mi], sbase + SM_A_HI * 2 + off);
                ldsm4(al[mi], sbase + SM_A_LO * 2 + off);
            }
#pragma unroll
            for (int ns = 0; ns < 2; ns++) {
                uint32_t wrow = kk * 16 + (lane & 15);
                uint32_t wcol = wn + ns * 16 + ((lane >> 4) << 3);
                uint32_t off = (wrow * 136 + wcol) * 2;
                ldsm4t(bh[ns * 2][0], bh[ns * 2][1], bh[ns * 2 + 1][0], bh[ns * 2 + 1][1],
                       sbase + SM_W_HI * 2 + off);
                ldsm4t(bl[ns * 2][0], bl[ns * 2][1], bl[ns * 2 + 1][0], bl[ns * 2 + 1][1],
                       sbase + SM_W_LO * 2 + off);
            }
#pragma unroll
            for (int mi = 0; mi < 4; mi++)
#pragma unroll
                for (int ni = 0; ni < 4; ni++) {
                    mma16816(acc[mi][ni], ah[mi], bh[ni]);
                    mma16816(acc[mi][ni], al[mi], bh[ni]);
                    mma16816(acc[mi][ni], ah[mi], bl[ni]);
                }
        }
    };

    load_stage(0, 0);
    cp_commit();
    for (int it = 0; it < nk; it++) {
        if (it + 1 < nk) {
            load_stage((it + 1) << 5, (it + 1) & 1);
            cp_commit();
            cp_wait1();
        } else {
            cp_wait0();
        }
        __syncthreads();
        compute_stage(it & 1);
        __syncthreads();
    }

    // epilogue: bias + relu + split + store bf16x2
#pragma unroll
    for (int ni = 0; ni < 4; ni++) {
        int c0 = n0 + wn + ni * 8 + (lane & 3) * 2;
        float2 b2 = *reinterpret_cast<const float2*>(bias + c0);
#pragma unroll
        for (int mi = 0; mi < 4; mi++) {
            int r0 = m0 + wm + mi * 16 + (lane >> 2);
#pragma unroll
            for (int hrow = 0; hrow < 2; hrow++) {
                int r = r0 + hrow * 8;
                float x0 = fmaxf(acc[mi][ni][hrow * 2 + 0] + b2.x, 0.f);
                float x1 = fmaxf(acc[mi][ni][hrow * 2 + 1] + b2.y, 0.f);
                __nv_bfloat162 h2, l2;
                split2(x0, h2.x, l2.x);
                split2(x1, h2.y, l2.y);
                size_t o = (size_t)r * ldc + c0;
                *reinterpret_cast<__nv_bfloat162*>(Chi + o) = h2;
                *reinterpret_cast<__nv_bfloat162*>(Clo + o) = l2;
            }
        }
    }
}

// ---------------------------------------------------------------------------
// dense [B,13] fp32 -> hi/lo planes [B,32] (zero padded)
// ---------------------------------------------------------------------------
__global__ __launch_bounds__(256) void conv_dense(
    const float* __restrict__ d, __nv_bfloat16* __restrict__ hi, __nv_bfloat16* __restrict__ lo)
{
    size_t idx = (size_t)blockIdx.x * 256 + threadIdx.x;
    if (idx >= (size_t)BATCH * 32) return;
    int row = idx >> 5, c = idx & 31;
    float x = (c < 13) ? d[(size_t)row * 13 + c] : 0.f;
    split2(x, hi[idx], lo[idx]);
}

// ---------------------------------------------------------------------------
// weights [K,N] fp32 -> hi/lo planes [Kpad,N] (zero padded rows)
// ---------------------------------------------------------------------------
__global__ __launch_bounds__(256) void conv_w(
    const float* __restrict__ w, __nv_bfloat16* __restrict__ hi, __nv_bfloat16* __restrict__ lo,
    int K, int N, int Kpad)
{
    size_t idx = (size_t)blockIdx.x * 256 + threadIdx.x;
    if (idx >= (size_t)Kpad * N) return;
    int k = idx / N, n = idx % N;
    float x = (k < K) ? w[(size_t)k * N + n] : 0.f;
    split2(x, hi[idx], lo[idx]);
}

// ---------------------------------------------------------------------------
// gather + Gram interaction. 1 warp per sample (2 samples / 64-thread block).
// Writes top input hi/lo planes (stride 512): [h(128) | triu(378) | zeros(6)]
// ---------------------------------------------------------------------------
__global__ __launch_bounds__(64) void interact2(
    const __nv_bfloat16* __restrict__ hhi, const __nv_bfloat16* __restrict__ hlo,
    const int* __restrict__ sidx, const float* __restrict__ emb,
    __nv_bfloat16* __restrict__ ohi, __nv_bfloat16* __restrict__ olo)
{
    __shared__ float comb[2][28][129];
    const int t = threadIdx.x;

    // load 2 samples x 28 rows x 128 (row 27 = zeros)
    for (int idx = t; idx < 2 * 28 * 128; idx += 64) {
        int s = idx / (28 * 128);
        int rem = idx - s * 28 * 128;
        int j = rem >> 7, d = rem & 127;
        size_t row = (size_t)blockIdx.x * 2 + s;
        float v;
        if (j == 0)
            v = __bfloat162float(hhi[row * 128 + d]) + __bfloat162float(hlo[row * 128 + d]);
        else if (j <= 26) {
            unsigned e = ((unsigned)sidx[row * 26 + (j - 1)]) & VOCAB_MASK;
            v = emb[(size_t)e * 128 + d];
        } else v = 0.f;
        comb[s][j][d] = v;
    }
    __syncthreads();

    const int s = t >> 5, lane = t & 31;
    const size_t row = (size_t)blockIdx.x * 2 + s;
    __nv_bfloat16* oh = ohi + row * 512;
    __nv_bfloat16* ol = olo + row * 512;

    // copy h planes into cols 0..127, zero 506..511
    for (int d = lane; d < 128; d += 32) {
        oh[d] = hhi[row * 128 + d];
        ol[d] = hlo[row * 128 + d];
    }
    if (lane < 6) {
        oh[506 + lane] = __float2bfloat16(0.f);
        ol[506 + lane] = __float2bfloat16(0.f);
    }

    if (lane < 28) {
        // map lane -> upper-triangular 4x4 tile (ty, tx), tx >= ty, 7x7 grid
        int ty = 0, rem = lane;
        while (rem >= 7 - ty) { rem -= 7 - ty; ty++; }
        int tx = ty + rem;
        int i0 = ty * 4, j0 = tx * 4;

        float a4[4], b4[4], acc[4][4];
#pragma unroll
        for (int a = 0; a < 4; a++)
#pragma unroll
            for (int b = 0; b < 4; b++) acc[a][b] = 0.f;

#pragma unroll 4
        for (int d = 0; d < 128; d++) {
#pragma unroll
            for (int a = 0; a < 4; a++) a4[a] = comb[s][i0 + a][d];
#pragma unroll
            for (int b = 0; b < 4; b++) b4[b] = comb[s][j0 + b][d];
#pragma unroll
            for (int a = 0; a < 4; a++)
#pragma unroll
                for (int b = 0; b < 4; b++)
                    acc[a][b] = fmaf(a4[a], b4[b], acc[a][b]);
        }
#pragma unroll
        for (int a = 0; a < 4; a++) {
            int i = i0 + a;
#pragma unroll
            for (int b = 0; b < 4; b++) {
                int j = j0 + b;
                if (j >= i && i < 27 && j < 27) {
                    int p = 27 * i - (i * (i - 1)) / 2 + (j - i);
                    __nv_bfloat16 h, l;
                    split2(acc[a][b], h, l);
                    oh[128 + p] = h;
                    ol[128 + p] = l;
                }
            }
        }
    }
}

// ---------------------------------------------------------------------------
// final layer: out[B] = (Ahi+Alo)[B,256] @ w[256] + b   (1 warp / row)
// ---------------------------------------------------------------------------
__global__ __launch_bounds__(256) void final_k(
    const __nv_bfloat16* __restrict__ Ahi, const __nv_bfloat16* __restrict__ Alo,
    const float* __restrict__ w, const float* __restrict__ bias, float* __restrict__ out)
{
    int warp = (blockIdx.x * blockDim.x + threadIdx.x) >> 5;
    int lane = threadIdx.x & 31;
    const __nv_bfloat16* ah = Ahi + (size_t)warp * 256;
    const __nv_bfloat16* al = Alo + (size_t)warp * 256;
    float s = 0.f;
#pragma unroll
    for (int i = 0; i < 8; i++) {
        int c = lane + i * 32;
        float a = __bfloat162float(ah[c]) + __bfloat162float(al[c]);
        s = fmaf(a, __ldg(&w[c]), s);
    }
#pragma unroll
    for (int o = 16; o; o >>= 1) s += __shfl_xor_sync(0xFFFFFFFFu, s, o);
    if (lane == 0) out[warp] = s + bias[0];
}

// ---------------------------------------------------------------------------
extern "C" void kernel_launch(void* const* d_in, const int* in_sizes, int n_in,
                              void* d_out, int out_size)
{
    const float* dense = (const float*)d_in[0];
    const int*   sidx  = (const int*)d_in[1];
    const float* emb   = (const float*)d_in[2];
    const float* bw0 = (const float*)d_in[3];  const float* bb0 = (const float*)d_in[4];
    const float* bw1 = (const float*)d_in[5];  const float* bb1 = (const float*)d_in[6];
    const float* bw2 = (const float*)d_in[7];  const float* bb2 = (const float*)d_in[8];
    const float* tw0 = (const float*)d_in[9];  const float* tb0 = (const float*)d_in[10];
    const float* tw1 = (const float*)d_in[11]; const float* tb1 = (const float*)d_in[12];
    const float* tw2 = (const float*)d_in[13]; const float* tb2 = (const float*)d_in[14];
    const float* tw3 = (const float*)d_in[15]; const float* tb3 = (const float*)d_in[16];
    const float* tw4 = (const float*)d_in[17]; const float* tb4 = (const float*)d_in[18];
    float* out = (float*)d_out;

    __nv_bfloat16 *pHi, *pLo, *qHi, *qLo, *hHi, *hLo, *wHi, *wLo;
    cudaGetSymbolAddress((void**)&pHi, g_p_hi);
    cudaGetSymbolAddress((void**)&pLo, g_p_lo);
    cudaGetSymbolAddress((void**)&qHi, g_q_hi);
    cudaGetSymbolAddress((void**)&qLo, g_q_lo);
    cudaGetSymbolAddress((void**)&hHi, g_h_hi);
    cudaGetSymbolAddress((void**)&hLo, g_h_lo);
    cudaGetSymbolAddress((void**)&wHi, g_w_hi);
    cudaGetSymbolAddress((void**)&wLo, g_w_lo);

    cudaFuncSetAttribute(gemm_bf16s, cudaFuncAttributeMaxDynamicSharedMemorySize, SMEM_BYTES);

    // weight plane offsets (Kpad x N)
    const size_t oL0 = 0;                        // 32x512
    const size_t oL1 = oL0 + 32 * 512;           // 512x256
    const size_t oL2 = oL1 + 512 * 256;          // 256x128
    const size_t oT0 = oL2 + 256 * 128;          // 512x1024
    const size_t oT1 = oT0 + 512 * 1024;         // 1024x1024
    const size_t oT2 = oT1 + 1024 * 1024;        // 1024x512
    const size_t oT3 = oT2 + 1024 * 512;         // 512x256

    auto cw = [&](const float* w, size_t off, int K, int N, int Kpad) {
        size_t n = (size_t)Kpad * N;
        conv_w<<<(unsigned)((n + 255) / 256), 256>>>(w, wHi + off, wLo + off, K, N, Kpad);
    };
    cw(bw0, oL0, 13, 512, 32);
    cw(bw1, oL1, 512, 256, 512);
    cw(bw2, oL2, 256, 128, 256);
    cw(tw0, oT0, 506, 1024, 512);
    cw(tw1, oT1, 1024, 1024, 1024);
    cw(tw2, oT2, 1024, 512, 1024);
    cw(tw3, oT3, 512, 256, 512);

    conv_dense<<<(BATCH * 32) / 256, 256>>>(dense, pHi, pLo);

    auto gemm = [&](const __nv_bfloat16* aH, const __nv_bfloat16* aL, size_t woff,
                    const float* bias, __nv_bfloat16* cH, __nv_bfloat16* cL,
                    int K, int N, int lda) {
        dim3 grid(N / 128, BATCH / 128);
        gemm_bf16s<<<grid, 256, SMEM_BYTES>>>(aH, aL, wHi + woff, wLo + woff,
                                              bias, cH, cL, K, N, lda, N);
    };

    // bottom MLP
    gemm(pHi, pLo, oL0, bb0, qHi, qLo, 32, 512, 32);
    gemm(qHi, qLo, oL1, bb1, pHi, pLo, 512, 256, 512);
    gemm(pHi, pLo, oL2, bb2, hHi, hLo, 256, 128, 256);

    // gather + interaction -> q planes (stride 512)
    interact2<<<BATCH / 2, 64>>>(hHi, hLo, sidx, emb, qHi, qLo);

    // top MLP
    gemm(qHi, qLo, oT0, tb0, pHi, pLo, 512, 1024, 512);
    gemm(pHi, pLo, oT1, tb1, qHi, qLo, 1024, 1024, 1024);
    gemm(qHi, qLo, oT2, tb2, pHi, pLo, 1024, 512, 1024);
    gemm(pHi, pLo, oT3, tb3, qHi, qLo, 512, 256, 512);

    // final 256 -> 1
    final_k<<<BATCH * 32 / 256, 256>>>(qHi, qLo, tw4, tb4, out);
}

// round 5
// speedup vs baseline: 3.2081x; 1.6173x over previous
#include <cuda_runtime.h>
#include <cuda_bf16.h>
#include <cstdint>

// ---------------------------------------------------------------------------
// DLRM small — split-bf16 GEMM chain.
// Primary path: tcgen05 (guarded, compiled only for sm_103a target).
// Fallback path: mma.sync HMMA (all other targets) — identical numerics.
// 3-pass split: acc += Ahi*Whi + Alo*Whi + Ahi*Wlo, fp32 accum.
// Weights pre-transposed to [N, Kpad] (K-major B operand).
// ---------------------------------------------------------------------------

#define BATCH 65536
#define VOCAB_MASK 0xFFFFFu

// ---------------- scratch ----------------
__device__ __nv_bfloat16 g_p_hi[(size_t)BATCH * 1024];
__device__ __nv_bfloat16 g_p_lo[(size_t)BATCH * 1024];
__device__ __nv_bfloat16 g_q_hi[(size_t)BATCH * 1024];
__device__ __nv_bfloat16 g_q_lo[(size_t)BATCH * 1024];
__device__ __nv_bfloat16 g_h_hi[(size_t)BATCH * 128];
__device__ __nv_bfloat16 g_h_lo[(size_t)BATCH * 128];
__device__ __nv_bfloat16 g_wt_hi[2424832];
__device__ __nv_bfloat16 g_wt_lo[2424832];

// ---------------- common helpers ----------------
__device__ __forceinline__ void split2(float x, __nv_bfloat16& h, __nv_bfloat16& l) {
    h = __float2bfloat16(x);
    l = __float2bfloat16(x - __bfloat162float(h));
}
__device__ __forceinline__ void cp16(uint32_t dst, const void* src) {
    asm volatile("cp.async.cg.shared.global [%0], [%1], 16;\n" :: "r"(dst), "l"(src));
}
__device__ __forceinline__ void cp_commit() { asm volatile("cp.async.commit_group;\n"); }
__device__ __forceinline__ void cp_wait0()  { asm volatile("cp.async.wait_group 0;\n" ::: "memory"); }
__device__ __forceinline__ void cp_wait1()  { asm volatile("cp.async.wait_group 1;\n" ::: "memory"); }

__device__ __forceinline__ void ldsm4(uint32_t* r, uint32_t addr) {
    asm volatile("ldmatrix.sync.aligned.m8n8.x4.shared.b16 {%0,%1,%2,%3}, [%4];\n"
        : "=r"(r[0]), "=r"(r[1]), "=r"(r[2]), "=r"(r[3]) : "r"(addr));
}
__device__ __forceinline__ void mma16816(float* d, const uint32_t* a, const uint32_t* b) {
    asm volatile(
        "mma.sync.aligned.m16n8k16.row.col.f32.bf16.bf16.f32 "
        "{%0,%1,%2,%3}, {%4,%5,%6,%7}, {%8,%9}, {%0,%1,%2,%3};\n"
        : "+f"(d[0]), "+f"(d[1]), "+f"(d[2]), "+f"(d[3])
        : "r"(a[0]), "r"(a[1]), "r"(a[2]), "r"(a[3]), "r"(b[0]), "r"(b[1]));
}

// shared loader: A tile [128 x 64k] + B tile [NT x 64k], hi/lo planes, SW128
template<int NT>
__device__ __forceinline__ void load_chunk(
    uint32_t sb,
    const __nv_bfloat16* __restrict__ Ahi, const __nv_bfloat16* __restrict__ Alo,
    const __nv_bfloat16* __restrict__ Bhi, const __nv_bfloat16* __restrict__ Blo,
    int m0, int n0, int K, int k0, int tid)
{
    constexpr uint32_t BPL = NT * 128u;   // bytes per B plane
    const int tot = 1024 + NT * 8;
    for (int q = tid; q < tot; q += 256) {
        if (q < 1024) {
            int row = q >> 3, seg = q & 7;
            uint32_t off = (uint32_t)(row * 128 + seg * 16);
            uint32_t sw = off ^ ((off >> 3) & 0x70u);
            size_t g = (size_t)(m0 + row) * K + k0 + seg * 8;
            cp16(sb + sw, Ahi + g);
            cp16(sb + 16384 + sw, Alo + g);
        } else {
            int r = q - 1024, row = r >> 3, seg = r & 7;
            uint32_t off = (uint32_t)(row * 128 + seg * 16);
            uint32_t sw = off ^ ((off >> 3) & 0x70u);
            size_t g = (size_t)(n0 + row) * K + k0 + seg * 8;
            cp16(sb + 32768 + sw, Bhi + g);
            cp16(sb + 32768 + BPL + sw, Blo + g);
        }
    }
}

// ---------------- tcgen05 helpers (sm_103a target only) ----------------
#if defined(__CUDA_ARCH_FEAT_SM103_ALL)
__device__ __forceinline__ uint64_t mkdesc(uint32_t addr) {
    const uint64_t base = 0x4000404000010000ULL;  // SW128, ver=1, SBO=64, LBO=1
    return base | ((uint64_t)(addr >> 4) & 0x3FFF);
}
__device__ __forceinline__ void mma_f16_ss(uint32_t d_tmem, uint64_t a_desc, uint64_t b_desc,
                                           uint32_t idesc, uint32_t enable) {
    asm volatile(
        "{\n\t"
        ".reg .pred p;\n\t"
        "setp.ne.u32 p, %5, 0;\n\t"
        "tcgen05.mma.cta_group::1.kind::f16 [%0], %1, %2, %3, {%4, %4, %4, %4}, p;\n\t"
        "}"
        :: "r"(d_tmem), "l"(a_desc), "l"(b_desc), "r"(idesc), "r"(0u), "r"(enable)
        : "memory");
}
#define TC_ALLOC(sa, n)   asm volatile("tcgen05.alloc.cta_group::1.sync.aligned.shared::cta.b32 [%0], %1;" :: "r"(sa), "r"(n) : "memory")
#define TC_DEALLOC(t, n)  asm volatile("tcgen05.dealloc.cta_group::1.sync.aligned.b32 %0, %1;" :: "r"(t), "r"(n))
#define TC_RELINQ()       asm volatile("tcgen05.relinquish_alloc_permit.cta_group::1.sync.aligned;")
#define TC_COMMIT(mb)     asm volatile("tcgen05.commit.cta_group::1.mbarrier::arrive::one.shared::cluster.b64 [%0];" :: "r"(mb) : "memory")
#define TC_FENCE_AFTER()  asm volatile("tcgen05.fence::after_thread_sync;" ::: "memory")
#define TC_WAIT_LD()      asm volatile("tcgen05.wait::ld.sync.aligned;" ::: "memory")
#define FENCE_ASYNC()     asm volatile("fence.proxy.async.shared::cta;" ::: "memory")
#define MB_INIT(mb, c)    asm volatile("mbarrier.init.shared.b64 [%0], %1;" :: "r"(mb), "r"(c) : "memory")

__device__ __forceinline__ void mb_wait(uint32_t mb, uint32_t parity) {
    asm volatile(
        "{\n\t"
        ".reg .pred P1;\n\t"
        "WAIT_LOOP_%=:\n\t"
        "mbarrier.try_wait.parity.acquire.cta.shared::cta.b64 P1, [%0], %1, 0x989680;\n\t"
        "@P1 bra.uni WAIT_DONE_%=;\n\t"
        "bra.uni WAIT_LOOP_%=;\n\t"
        "WAIT_DONE_%=:\n\t"
        "}"
        :: "r"(mb), "r"(parity) : "memory");
}
__device__ __forceinline__ void ldtm32(uint32_t* r, uint32_t ta) {
    asm volatile(
        "tcgen05.ld.sync.aligned.32x32b.x32.b32 "
        "{%0,%1,%2,%3,%4,%5,%6,%7,%8,%9,%10,%11,%12,%13,%14,%15,"
        "%16,%17,%18,%19,%20,%21,%22,%23,%24,%25,%26,%27,%28,%29,%30,%31}, [%32];"
        : "=r"(r[0]), "=r"(r[1]), "=r"(r[2]), "=r"(r[3]), "=r"(r[4]), "=r"(r[5]), "=r"(r[6]), "=r"(r[7]),
          "=r"(r[8]), "=r"(r[9]), "=r"(r[10]), "=r"(r[11]), "=r"(r[12]), "=r"(r[13]), "=r"(r[14]), "=r"(r[15]),
          "=r"(r[16]), "=r"(r[17]), "=r"(r[18]), "=r"(r[19]), "=r"(r[20]), "=r"(r[21]), "=r"(r[22]), "=r"(r[23]),
          "=r"(r[24]), "=r"(r[25]), "=r"(r[26]), "=r"(r[27]), "=r"(r[28]), "=r"(r[29]), "=r"(r[30]), "=r"(r[31])
        : "r"(ta));
}
// idesc: F32 acc, BF16 a/b, N=128/dispatch, M=128  => 0x8200490
constexpr uint32_t IDESC = (1u << 4) | (1u << 7) | (1u << 10) | (16u << 17) | (8u << 24);
#endif

// ---------------------------------------------------------------------------
// Unified GEMM: C[M,N] = relu(A@Wt^T + bias)
// A: [M,K] hi/lo planes (K mult of 64). Wt: [N,K] hi/lo planes.
// grid = (N/NT, M/128), 256 threads.
// ---------------------------------------------------------------------------
template<int NT>
__global__ __launch_bounds__(256, 1) void gemm_tc(
    const __nv_bfloat16* __restrict__ Ahi, const __nv_bfloat16* __restrict__ Alo,
    const __nv_bfloat16* __restrict__ Bhi, const __nv_bfloat16* __restrict__ Blo,
    const float* __restrict__ bias,
    __nv_bfloat16* __restrict__ Chi, __nv_bfloat16* __restrict__ Clo,
    int K, int ldc)
{
    extern __shared__ __align__(16) char smem_raw[];
    uint32_t sraw = (uint32_t)__cvta_generic_to_shared(smem_raw);
    const uint32_t s0 = (sraw + 1023u) & ~1023u;
    const uint32_t s_tile = s0 + 1024;
    constexpr uint32_t STG = 32768u + 2u * NT * 128u;

    const int tid = threadIdx.x, w = tid >> 5, lane = tid & 31;
    const int m0 = blockIdx.y * 128;
    const int n0 = blockIdx.x * NT;
    const int nk = K >> 6;

#if defined(__CUDA_ARCH_FEAT_SM103_ALL)
    // ================= tcgen05 path =================
    constexpr int nns = NT / 128;
    if (tid == 0) { MB_INIT(s0 + 8, 1); MB_INIT(s0 + 16, 1); }
    if (w == 0) TC_ALLOC(s0, 512);
    __syncthreads();
    uint32_t tmem;
    asm volatile("ld.shared.b32 %0, [%1];" : "=r"(tmem) : "r"(s0));

    load_chunk<NT>(s_tile, Ahi, Alo, Bhi, Blo, m0, n0, K, 0, tid);
    cp_commit();
    if (nk > 1) {
        load_chunk<NT>(s_tile + STG, Ahi, Alo, Bhi, Blo, m0, n0, K, 64, tid);
        cp_commit();
    }

    int ph[2] = {0, 0};
    for (int it = 0; it < nk; it++) {
        const int st = it & 1;
        if (it + 1 < nk) cp_wait1(); else cp_wait0();
        __syncthreads();
        if (tid == 0) {
            FENCE_ASYNC();
            const uint32_t sb = s_tile + st * STG;
            const uint64_t aD[2] = { mkdesc(sb), mkdesc(sb + 16384) };
            const uint64_t bD[2] = { mkdesc(sb + 32768), mkdesc(sb + 32768 + NT * 128u) };
            for (int p = 0; p < 3; p++) {
                uint64_t ad = aD[p == 1], bd = bD[p == 2];
                for (int ns = 0; ns < nns; ns++)
                    for (int k = 0; k < 4; k++)
                        mma_f16_ss(tmem + ns * 128, ad + k * 2, bd + ns * 1024 + k * 2,
                                   IDESC, (uint32_t)(it | p | k));
            }
            TC_COMMIT(s0 + 8 + st * 8);
        }
        if (it + 2 < nk) {
            mb_wait(s0 + 8 + st * 8, ph[st]); ph[st] ^= 1;
            load_chunk<NT>(s_tile + st * STG, Ahi, Alo, Bhi, Blo, m0, n0, K, (it + 2) << 6, tid);
            cp_commit();
        }
    }
    const int stl = (nk - 1) & 1;
    mb_wait(s0 + 8 + stl * 8, ph[stl]);
    TC_FENCE_AFTER();

    // epilogue: warp w -> rows (w&3)*32 (its subpartition), col half (w>>2)
    {
        float* ep = reinterpret_cast<float*>(smem_raw + (s_tile - sraw) + (size_t)w * 32 * 33 * 4);
        const int sp = w & 3;
        const int c_beg = (w >> 2) * (NT / 2);
        for (int c0 = c_beg; c0 < c_beg + NT / 2; c0 += 32) {
            uint32_t r[32];
            ldtm32(r, tmem + c0);
            TC_WAIT_LD();
#pragma unroll
            for (int j = 0; j < 32; j++) ep[lane * 33 + j] = __uint_as_float(r[j]);
            __syncwarp();
            const float bv = bias[n0 + c0 + lane];
#pragma unroll
            for (int rr = 0; rr < 32; rr++) {
                float x = fmaxf(ep[rr * 33 + lane] + bv, 0.f);
                __nv_bfloat16 h, l; split2(x, h, l);
                size_t o = (size_t)(m0 + sp * 32 + rr) * ldc + n0 + c0 + lane;
                Chi[o] = h; Clo[o] = l;
            }
            __syncwarp();
        }
    }
    __syncthreads();
    if (w == 0) { TC_RELINQ(); TC_DEALLOC(tmem, 512); }
#else
    // ================= HMMA fallback =================
    constexpr int NW = NT / 4;            // N per warp (64 or 32)
    constexpr int N8 = NW / 8;            // 8-wide n subtiles per warp
    const int wm = (w & 1) * 64;          // warp M offset
    const int wn = (w >> 1) * NW;         // warp N offset

    float acc[4][N8][4];
#pragma unroll
    for (int i = 0; i < 4; i++)
#pragma unroll
        for (int j = 0; j < N8; j++)
#pragma unroll
            for (int r = 0; r < 4; r++) acc[i][j][r] = 0.f;

    load_chunk<NT>(s_tile, Ahi, Alo, Bhi, Blo, m0, n0, K, 0, tid);
    cp_commit();
    if (nk > 1) {
        load_chunk<NT>(s_tile + STG, Ahi, Alo, Bhi, Blo, m0, n0, K, 64, tid);
        cp_commit();
    }

    for (int it = 0; it < nk; it++) {
        const int st = it & 1;
        if (it + 1 < nk) cp_wait1(); else cp_wait0();
        __syncthreads();
        const uint32_t sb = s_tile + st * STG;
#pragma unroll
        for (int kk = 0; kk < 4; kk++) {
            const uint32_t kb = kk * 32 + ((lane >> 4) * 16);
            uint32_t ah[4][4], al[4][4], bh[N8][2], bl[N8][2];
#pragma unroll
            for (int mi = 0; mi < 4; mi++) {
                uint32_t off = (uint32_t)((wm + mi * 16 + (lane & 15)) * 128) + kb;
                uint32_t sw = off ^ ((off >> 3) & 0x70u);
                ldsm4(ah[mi], sb + sw);
                ldsm4(al[mi], sb + 16384 + sw);
            }
#pragma unroll
            for (int nt = 0; nt < N8 / 2; nt++) {
                uint32_t off = (uint32_t)((wn + nt * 16 + (lane & 15)) * 128) + kb;
                uint32_t sw = off ^ ((off >> 3) & 0x70u);
                uint32_t t[4];
                ldsm4(t, sb + 32768 + sw);
                bh[nt * 2][0] = t[0]; bh[nt * 2][1] = t[2];
                bh[nt * 2 + 1][0] = t[1]; bh[nt * 2 + 1][1] = t[3];
                ldsm4(t, sb + 32768 + NT * 128u + sw);
                bl[nt * 2][0] = t[0]; bl[nt * 2][1] = t[2];
                bl[nt * 2 + 1][0] = t[1]; bl[nt * 2 + 1][1] = t[3];
            }
#pragma unroll
            for (int mi = 0; mi < 4; mi++)
#pragma unroll
                for (int j = 0; j < N8; j++) {
                    mma16816(acc[mi][j], ah[mi], bh[j]);
                    mma16816(acc[mi][j], al[mi], bh[j]);
                    mma16816(acc[mi][j], ah[mi], bl[j]);
                }
        }
        __syncthreads();
        if (it + 2 < nk) {
            load_chunk<NT>(s_tile + st * STG, Ahi, Alo, Bhi, Blo, m0, n0, K, (it + 2) << 6, tid);
            cp_commit();
        }
    }

    // epilogue
#pragma unroll
    for (int j = 0; j < N8; j++) {
        int c0 = n0 + wn + j * 8 + (lane & 3) * 2;
        float2 b2 = *reinterpret_cast<const float2*>(bias + c0);
#pragma unroll
        for (int mi = 0; mi < 4; mi++) {
            int r0 = m0 + wm + mi * 16 + (lane >> 2);
#pragma unroll
            for (int hrow = 0; hrow < 2; hrow++) {
                int r = r0 + hrow * 8;
                float x0 = fmaxf(acc[mi][j][hrow * 2 + 0] + b2.x, 0.f);
                float x1 = fmaxf(acc[mi][j][hrow * 2 + 1] + b2.y, 0.f);
                __nv_bfloat162 h2, l2;
                split2(x0, h2.x, l2.x);
                split2(x1, h2.y, l2.y);
                size_t o = (size_t)r * ldc + c0;
                *reinterpret_cast<__nv_bfloat162*>(Chi + o) = h2;
                *reinterpret_cast<__nv_bfloat162*>(Clo + o) = l2;
            }
        }
    }
#endif
}

// ---------------------------------------------------------------------------
__global__ __launch_bounds__(256) void conv_dense(
    const float* __restrict__ d, __nv_bfloat16* __restrict__ hi, __nv_bfloat16* __restrict__ lo)
{
    size_t idx = (size_t)blockIdx.x * 256 + threadIdx.x;
    if (idx >= (size_t)BATCH * 64) return;
    int row = (int)(idx >> 6), c = (int)(idx & 63);
    float x = (c < 13) ? d[(size_t)row * 13 + c] : 0.f;
    split2(x, hi[idx], lo[idx]);
}

__global__ __launch_bounds__(256) void conv_wT(
    const float* __restrict__ w, __nv_bfloat16* __restrict__ hi, __nv_bfloat16* __restrict__ lo,
    int K, int N, int Kpad)
{
    size_t idx = (size_t)blockIdx.x * 256 + threadIdx.x;
    if (idx >= (size_t)N * Kpad) return;
    int n = (int)(idx / Kpad), k = (int)(idx % Kpad);
    float x = (k < K) ? w[(size_t)k * N + n] : 0.f;
    split2(x, hi[idx], lo[idx]);
}

// ---------------------------------------------------------------------------
__global__ __launch_bounds__(64) void interact2(
    const __nv_bfloat16* __restrict__ hhi, const __nv_bfloat16* __restrict__ hlo,
    const int* __restrict__ sidx, const float* __restrict__ emb,
    __nv_bfloat16* __restrict__ ohi, __nv_bfloat16* __restrict__ olo)
{
    __shared__ float comb[2][28][129];
    const int t = threadIdx.x;

    for (int idx = t; idx < 2 * 28 * 128; idx += 64) {
        int s = idx / (28 * 128);
        int rem = idx - s * 28 * 128;
        int j = rem >> 7, d = rem & 127;
        size_t row = (size_t)blockIdx.x * 2 + s;
        float v;
        if (j == 0)
            v = __bfloat162float(hhi[row * 128 + d]) + __bfloat162float(hlo[row * 128 + d]);
        else if (j <= 26) {
            unsigned e = ((unsigned)sidx[row * 26 + (j - 1)]) & VOCAB_MASK;
            v = emb[(size_t)e * 128 + d];
        } else v = 0.f;
        comb[s][j][d] = v;
    }
    __syncthreads();

    const int s = t >> 5, lane = t & 31;
    const size_t row = (size_t)blockIdx.x * 2 + s;
    __nv_bfloat16* oh = ohi + row * 512;
    __nv_bfloat16* ol = olo + row * 512;

    for (int d = lane; d < 128; d += 32) {
        oh[d] = hhi[row * 128 + d];
        ol[d] = hlo[row * 128 + d];
    }
    if (lane < 6) {
        oh[506 + lane] = __float2bfloat16(0.f);
        ol[506 + lane] = __float2bfloat16(0.f);
    }

    if (lane < 28) {
        int ty = 0, rem = lane;
        while (rem >= 7 - ty) { rem -= 7 - ty; ty++; }
        int tx = ty + rem;
        int i0 = ty * 4, j0 = tx * 4;

        float a4[4], b4[4], acc[4][4];
#pragma unroll
        for (int a = 0; a < 4; a++)
#pragma unroll
            for (int b = 0; b < 4; b++) acc[a][b] = 0.f;

#pragma unroll 4
        for (int d = 0; d < 128; d++) {
#pragma unroll
            for (int a = 0; a < 4; a++) a4[a] = comb[s][i0 + a][d];
#pragma unroll
            for (int b = 0; b < 4; b++) b4[b] = comb[s][j0 + b][d];
#pragma unroll
            for (int a = 0; a < 4; a++)
#pragma unroll
                for (int b = 0; b < 4; b++)
                    acc[a][b] = fmaf(a4[a], b4[b], acc[a][b]);
        }
#pragma unroll
        for (int a = 0; a < 4; a++) {
            int i = i0 + a;
#pragma unroll
            for (int b = 0; b < 4; b++) {
                int j = j0 + b;
                if (j >= i && i < 27 && j < 27) {
                    int p = 27 * i - (i * (i - 1)) / 2 + (j - i);
                    __nv_bfloat16 h, l;
                    split2(acc[a][b], h, l);
                    oh[128 + p] = h;
                    ol[128 + p] = l;
                }
            }
        }
    }
}

// ---------------------------------------------------------------------------
__global__ __launch_bounds__(256) void final_k(
    const __nv_bfloat16* __restrict__ Ahi, const __nv_bfloat16* __restrict__ Alo,
    const float* __restrict__ w, const float* __restrict__ bias, float* __restrict__ out)
{
    int warp = (blockIdx.x * blockDim.x + threadIdx.x) >> 5;
    int lane = threadIdx.x & 31;
    const __nv_bfloat16* ah = Ahi + (size_t)warp * 256;
    const __nv_bfloat16* al = Alo + (size_t)warp * 256;
    float s = 0.f;
#pragma unroll
    for (int i = 0; i < 8; i++) {
        int c = lane + i * 32;
        float a = __bfloat162float(ah[c]) + __bfloat162float(al[c]);
        s = fmaf(a, __ldg(&w[c]), s);
    }
#pragma unroll
    for (int o = 16; o; o >>= 1) s += __shfl_xor_sync(0xFFFFFFFFu, s, o);
    if (lane == 0) out[warp] = s + bias[0];
}

// ---------------------------------------------------------------------------
extern "C" void kernel_launch(void* const* d_in, const int* in_sizes, int n_in,
                              void* d_out, int out_size)
{
    const float* dense = (const float*)d_in[0];
    const int*   sidx  = (const int*)d_in[1];
    const float* emb   = (const float*)d_in[2];
    const float* bw0 = (const float*)d_in[3];  const float* bb0 = (const float*)d_in[4];
    const float* bw1 = (const float*)d_in[5];  const float* bb1 = (const float*)d_in[6];
    const float* bw2 = (const float*)d_in[7];  const float* bb2 = (const float*)d_in[8];
    const float* tw0 = (const float*)d_in[9];  const float* tb0 = (const float*)d_in[10];
    const float* tw1 = (const float*)d_in[11]; const float* tb1 = (const float*)d_in[12];
    const float* tw2 = (const float*)d_in[13]; const float* tb2 = (const float*)d_in[14];
    const float* tw3 = (const float*)d_in[15]; const float* tb3 = (const float*)d_in[16];
    const float* tw4 = (const float*)d_in[17]; const float* tb4 = (const float*)d_in[18];
    float* out = (float*)d_out;

    __nv_bfloat16 *pHi, *pLo, *qHi, *qLo, *hHi, *hLo, *wtHi, *wtLo;
    cudaGetSymbolAddress((void**)&pHi, g_p_hi);
    cudaGetSymbolAddress((void**)&pLo, g_p_lo);
    cudaGetSymbolAddress((void**)&qHi, g_q_hi);
    cudaGetSymbolAddress((void**)&qLo, g_q_lo);
    cudaGetSymbolAddress((void**)&hHi, g_h_hi);
    cudaGetSymbolAddress((void**)&hLo, g_h_lo);
    cudaGetSymbolAddress((void**)&wtHi, g_wt_hi);
    cudaGetSymbolAddress((void**)&wtLo, g_wt_lo);

    const int SM256 = 2048 + 2 * (32768 + 2 * 256 * 128);  // 198656
    const int SM128 = 2048 + 2 * (32768 + 2 * 128 * 128);  // 133120
    cudaFuncSetAttribute(gemm_tc<256>, cudaFuncAttributeMaxDynamicSharedMemorySize, SM256);
    cudaFuncSetAttribute(gemm_tc<128>, cudaFuncAttributeMaxDynamicSharedMemorySize, SM128);

    // transposed weight plane offsets ([N, Kpad])
    const size_t o0 = 0;                    // 512 x 64
    const size_t o1 = o0 + 512 * 64;        // 256 x 512
    const size_t o2 = o1 + 256 * 512;       // 128 x 256
    const size_t o3 = o2 + 128 * 256;       // 1024 x 512
    const size_t o4 = o3 + 1024 * 512;      // 1024 x 1024
    const size_t o5 = o4 + 1024 * 1024;     // 512 x 1024
    const size_t o6 = o5 + 512 * 1024;      // 256 x 512

    auto cw = [&](const float* w, size_t off, int K, int N, int Kpad) {
        size_t n = (size_t)N * Kpad;
        conv_wT<<<(unsigned)((n + 255) / 256), 256>>>(w, wtHi + off, wtLo + off, K, N, Kpad);
    };
    cw(bw0, o0, 13, 512, 64);
    cw(bw1, o1, 512, 256, 512);
    cw(bw2, o2, 256, 128, 256);
    cw(tw0, o3, 506, 1024, 512);
    cw(tw1, o4, 1024, 1024, 1024);
    cw(tw2, o5, 1024, 512, 1024);
    cw(tw3, o6, 512, 256, 512);

    conv_dense<<<(BATCH * 64) / 256, 256>>>(dense, pHi, pLo);

    auto G = [&](const __nv_bfloat16* aH, const __nv_bfloat16* aL, size_t woff,
                 const float* bias, __nv_bfloat16* cH, __nv_bfloat16* cL, int K, int N) {
        if (N >= 256) {
            dim3 grid(N / 256, BATCH / 128);
            gemm_tc<256><<<grid, 256, SM256>>>(aH, aL, wtHi + woff, wtLo + woff,
                                               bias, cH, cL, K, N);
        } else {
            dim3 grid(N / 128, BATCH / 128);
            gemm_tc<128><<<grid, 256, SM128>>>(aH, aL, wtHi + woff, wtLo + woff,
                                               bias, cH, cL, K, N);
        }
    };

    // bottom MLP
    G(pHi, pLo, o0, bb0, qHi, qLo, 64, 512);
    G(qHi, qLo, o1, bb1, pHi, pLo, 512, 256);
    G(pHi, pLo, o2, bb2, hHi, hLo, 256, 128);

    // gather + interaction -> q planes (stride 512)
    interact2<<<BATCH / 2, 64>>>(hHi, hLo, sidx, emb, qHi, qLo);

    // top MLP
    G(qHi, qLo, o3, tb0, pHi, pLo, 512, 1024);
    G(pHi, pLo, o4, tb1, qHi, qLo, 1024, 1024);
    G(qHi, qLo, o5, tb2, pHi, pLo, 1024, 512);
    G(pHi, pLo, o6, tb3, qHi, qLo, 512, 256);

    // final 256 -> 1
    final_k<<<BATCH * 32 / 256, 256>>>(qHi, qLo, tw4, tb4, out);
}

// round 6
// speedup vs baseline: 3.3129x; 1.0327x over previous
#include <cuda_runtime.h>
#include <cuda_bf16.h>
#include <cstdint>

// ---------------------------------------------------------------------------
// DLRM small — split-bf16 GEMM chain.
// Primary path: tcgen05 (guarded; compiled only when the sm_103a feature set
// exists). Loads use LDG.128 -> reg staging -> STS.128 (cp.async issue rate
// of 8 cyc/op/SMSP was the measured bottleneck).
// Fallback path: mma.sync HMMA with cp.async (unchanged, controlled no-op).
// 3-pass split: acc += Ahi*Whi + Alo*Whi + Ahi*Wlo, fp32 accum.
// Weights pre-transposed to [N, Kpad] (K-major B operand).
// ---------------------------------------------------------------------------

#define BATCH 65536
#define VOCAB_MASK 0xFFFFFu

// ---------------- scratch ----------------
__device__ __nv_bfloat16 g_p_hi[(size_t)BATCH * 1024];
__device__ __nv_bfloat16 g_p_lo[(size_t)BATCH * 1024];
__device__ __nv_bfloat16 g_q_hi[(size_t)BATCH * 1024];
__device__ __nv_bfloat16 g_q_lo[(size_t)BATCH * 1024];
__device__ __nv_bfloat16 g_h_hi[(size_t)BATCH * 128];
__device__ __nv_bfloat16 g_h_lo[(size_t)BATCH * 128];
__device__ __nv_bfloat16 g_wt_hi[2424832];
__device__ __nv_bfloat16 g_wt_lo[2424832];

// ---------------- common helpers ----------------
__device__ __forceinline__ void split2(float x, __nv_bfloat16& h, __nv_bfloat16& l) {
    h = __float2bfloat16(x);
    l = __float2bfloat16(x - __bfloat162float(h));
}
__device__ __forceinline__ void cp16(uint32_t dst, const void* src) {
    asm volatile("cp.async.cg.shared.global [%0], [%1], 16;\n" :: "r"(dst), "l"(src));
}
__device__ __forceinline__ void cp_commit() { asm volatile("cp.async.commit_group;\n"); }
__device__ __forceinline__ void cp_wait0()  { asm volatile("cp.async.wait_group 0;\n" ::: "memory"); }
__device__ __forceinline__ void cp_wait1()  { asm volatile("cp.async.wait_group 1;\n" ::: "memory"); }

__device__ __forceinline__ void ldsm4(uint32_t* r, uint32_t addr) {
    asm volatile("ldmatrix.sync.aligned.m8n8.x4.shared.b16 {%0,%1,%2,%3}, [%4];\n"
        : "=r"(r[0]), "=r"(r[1]), "=r"(r[2]), "=r"(r[3]) : "r"(addr));
}
__device__ __forceinline__ void mma16816(float* d, const uint32_t* a, const uint32_t* b) {
    asm volatile(
        "mma.sync.aligned.m16n8k16.row.col.f32.bf16.bf16.f32 "
        "{%0,%1,%2,%3}, {%4,%5,%6,%7}, {%8,%9}, {%0,%1,%2,%3};\n"
        : "+f"(d[0]), "+f"(d[1]), "+f"(d[2]), "+f"(d[3])
        : "r"(a[0]), "r"(a[1]), "r"(a[2]), "r"(a[3]), "r"(b[0]), "r"(b[1]));
}

// cp.async chunk loader (fallback path only)
template<int NT>
__device__ __forceinline__ void load_chunk_ca(
    uint32_t sb,
    const __nv_bfloat16* __restrict__ Ahi, const __nv_bfloat16* __restrict__ Alo,
    const __nv_bfloat16* __restrict__ Bhi, const __nv_bfloat16* __restrict__ Blo,
    int m0, int n0, int K, int k0, int tid)
{
    constexpr uint32_t BPL = NT * 128u;
    const int tot = 1024 + NT * 8;
    for (int q = tid; q < tot; q += 256) {
        if (q < 1024) {
            int row = q >> 3, seg = q & 7;
            uint32_t off = (uint32_t)(row * 128 + seg * 16);
            uint32_t sw = off ^ ((off >> 3) & 0x70u);
            size_t g = (size_t)(m0 + row) * K + k0 + seg * 8;
            cp16(sb + sw, Ahi + g);
            cp16(sb + 16384 + sw, Alo + g);
        } else {
            int r = q - 1024, row = r >> 3, seg = r & 7;
            uint32_t off = (uint32_t)(row * 128 + seg * 16);
            uint32_t sw = off ^ ((off >> 3) & 0x70u);
            size_t g = (size_t)(n0 + row) * K + k0 + seg * 8;
            cp16(sb + 32768 + sw, Bhi + g);
            cp16(sb + 32768 + BPL + sw, Blo + g);
        }
    }
}

// ---------------- tcgen05 helpers (sm_103a feature target only) ----------------
#if defined(__CUDA_ARCH_FEAT_SM103_ALL)
__device__ __forceinline__ uint64_t mkdesc(uint32_t addr) {
    const uint64_t base = 0x4000404000010000ULL;  // SW128, ver=1, SBO=64, LBO=1
    return base | ((uint64_t)(addr >> 4) & 0x3FFF);
}
__device__ __forceinline__ void mma_f16_ss(uint32_t d_tmem, uint64_t a_desc, uint64_t b_desc,
                                           uint32_t idesc, uint32_t enable) {
    asm volatile(
        "{\n\t"
        ".reg .pred p;\n\t"
        "setp.ne.u32 p, %5, 0;\n\t"
        "tcgen05.mma.cta_group::1.kind::f16 [%0], %1, %2, %3, {%4, %4, %4, %4}, p;\n\t"
        "}"
        :: "r"(d_tmem), "l"(a_desc), "l"(b_desc), "r"(idesc), "r"(0u), "r"(enable)
        : "memory");
}
#define TC_ALLOC(sa, n)   asm volatile("tcgen05.alloc.cta_group::1.sync.aligned.shared::cta.b32 [%0], %1;" :: "r"(sa), "r"(n) : "memory")
#define TC_DEALLOC(t, n)  asm volatile("tcgen05.dealloc.cta_group::1.sync.aligned.b32 %0, %1;" :: "r"(t), "r"(n))
#define TC_RELINQ()       asm volatile("tcgen05.relinquish_alloc_permit.cta_group::1.sync.aligned;")
#define TC_COMMIT(mb)     asm volatile("tcgen05.commit.cta_group::1.mbarrier::arrive::one.shared::cluster.b64 [%0];" :: "r"(mb) : "memory")
#define TC_FENCE_AFTER()  asm volatile("tcgen05.fence::after_thread_sync;" ::: "memory")
#define TC_WAIT_LD()      asm volatile("tcgen05.wait::ld.sync.aligned;" ::: "memory")
#define FENCE_ASYNC()     asm volatile("fence.proxy.async.shared::cta;" ::: "memory")
#define MB_INIT(mb, c)    asm volatile("mbarrier.init.shared.b64 [%0], %1;" :: "r"(mb), "r"(c) : "memory")

__device__ __forceinline__ void mb_wait(uint32_t mb, uint32_t parity) {
    asm volatile(
        "{\n\t"
        ".reg .pred P1;\n\t"
        "WAIT_LOOP_%=:\n\t"
        "mbarrier.try_wait.parity.acquire.cta.shared::cta.b64 P1, [%0], %1, 0x989680;\n\t"
        "@P1 bra.uni WAIT_DONE_%=;\n\t"
        "bra.uni WAIT_LOOP_%=;\n\t"
        "WAIT_DONE_%=:\n\t"
        "}"
        :: "r"(mb), "r"(parity) : "memory");
}
__device__ __forceinline__ void ldtm32(uint32_t* r, uint32_t ta) {
    asm volatile(
        "tcgen05.ld.sync.aligned.32x32b.x32.b32 "
        "{%0,%1,%2,%3,%4,%5,%6,%7,%8,%9,%10,%11,%12,%13,%14,%15,"
        "%16,%17,%18,%19,%20,%21,%22,%23,%24,%25,%26,%27,%28,%29,%30,%31}, [%32];"
        : "=r"(r[0]), "=r"(r[1]), "=r"(r[2]), "=r"(r[3]), "=r"(r[4]), "=r"(r[5]), "=r"(r[6]), "=r"(r[7]),
          "=r"(r[8]), "=r"(r[9]), "=r"(r[10]), "=r"(r[11]), "=r"(r[12]), "=r"(r[13]), "=r"(r[14]), "=r"(r[15]),
          "=r"(r[16]), "=r"(r[17]), "=r"(r[18]), "=r"(r[19]), "=r"(r[20]), "=r"(r[21]), "=r"(r[22]), "=r"(r[23]),
          "=r"(r[24]), "=r"(r[25]), "=r"(r[26]), "=r"(r[27]), "=r"(r[28]), "=r"(r[29]), "=r"(r[30]), "=r"(r[31])
        : "r"(ta));
}
// idesc: F32 acc, BF16 a/b, N=128/dispatch, M=128  => 0x8200490
constexpr uint32_t IDESC = (1u << 4) | (1u << 7) | (1u << 10) | (16u << 17) | (8u << 24);
#endif

// ---------------------------------------------------------------------------
// Unified GEMM: C[M,N] = relu(A@Wt^T + bias)
// A: [M,K] hi/lo planes. Wt: [N,K] hi/lo planes. K is a template constant.
// grid = (N/NT, M/128), 256 threads.
// ---------------------------------------------------------------------------
template<int NT, int K>
__global__ __launch_bounds__(256, 1) void gemm_tc(
    const __nv_bfloat16* __restrict__ Ahi, const __nv_bfloat16* __restrict__ Alo,
    const __nv_bfloat16* __restrict__ Bhi, const __nv_bfloat16* __restrict__ Blo,
    const float* __restrict__ bias,
    __nv_bfloat16* __restrict__ Chi, __nv_bfloat16* __restrict__ Clo,
    int ldc)
{
    extern __shared__ __align__(16) char smem_raw[];
    uint32_t sraw = (uint32_t)__cvta_generic_to_shared(smem_raw);
    const uint32_t s0 = (sraw + 1023u) & ~1023u;
    const uint32_t s_tile = s0 + 1024;
    constexpr uint32_t STG = 32768u + 2u * NT * 128u;
    constexpr int nk = K / 64;

    const int tid = threadIdx.x, w = tid >> 5, lane = tid & 31;
    const int m0 = blockIdx.y * 128;
    const int n0 = blockIdx.x * NT;

#if defined(__CUDA_ARCH_FEAT_SM103_ALL)
    // ================= tcgen05 path: LDG->regs->STS staging =================
    constexpr int nns = NT / 128;
    constexpr int NB = NT / 32;            // B uint4 per plane per thread
    constexpr size_t GSTR = (size_t)32 * K * 2;  // global byte stride per r

    if (tid == 0) { MB_INIT(s0 + 8, 1); MB_INIT(s0 + 16, 1); }
    if (w == 0) TC_ALLOC(s0, 512);
    __syncthreads();
    uint32_t tmem;
    asm volatile("ld.shared.b32 %0, [%1];" : "=r"(tmem) : "r"(s0));

    // per-thread invariant bases
    const int row0 = tid >> 3, seg = tid & 7;
    const char* gAh = (const char*)(Ahi + (size_t)(m0 + row0) * K + seg * 8);
    const char* gAl = (const char*)(Alo + (size_t)(m0 + row0) * K + seg * 8);
    const char* gBh = (const char*)(Bhi + (size_t)(n0 + row0) * K + seg * 8);
    const char* gBl = (const char*)(Blo + (size_t)(n0 + row0) * K + seg * 8);
    uint32_t off0 = (uint32_t)(row0 * 128 + seg * 16);
    const uint32_t sA = off0 ^ ((off0 >> 3) & 0x70u);   // also valid for B rows
    char* const smt = smem_raw + (s_tile - sraw);

    uint4 rAh[4], rAl[4], rBh[NB], rBl[NB];

    auto ldg_chunk = [&](int it) {
        const size_t kb = (size_t)(it << 6) * 2;
#pragma unroll
        for (int r = 0; r < 4; r++) {
            rAh[r] = *(const uint4*)(gAh + kb + r * GSTR);
            rAl[r] = *(const uint4*)(gAl + kb + r * GSTR);
        }
#pragma unroll
        for (int r = 0; r < NB; r++) {
            rBh[r] = *(const uint4*)(gBh + kb + r * GSTR);
            rBl[r] = *(const uint4*)(gBl + kb + r * GSTR);
        }
    };
    auto sts_chunk = [&](int st) {
        char* sb = smt + st * STG;
#pragma unroll
        for (int r = 0; r < 4; r++) {
            *(uint4*)(sb + sA + r * 4096) = rAh[r];
            *(uint4*)(sb + 16384 + sA + r * 4096) = rAl[r];
        }
#pragma unroll
        for (int r = 0; r < NB; r++) {
            *(uint4*)(sb + 32768 + sA + r * 4096) = rBh[r];
            *(uint4*)(sb + 32768 + NT * 128 + sA + r * 4096) = rBl[r];
        }
    };
    auto mma_chunk = [&](int it, int st) {
        if (tid == 0) {
            FENCE_ASYNC();
            const uint32_t sb = s_tile + st * STG;
            const uint64_t aD[2] = { mkdesc(sb), mkdesc(sb + 16384) };
            const uint64_t bD[2] = { mkdesc(sb + 32768), mkdesc(sb + 32768 + NT * 128u) };
#pragma unroll
            for (int p = 0; p < 3; p++) {
                uint64_t ad = aD[p == 1], bd = bD[p == 2];
#pragma unroll
                for (int ns = 0; ns < nns; ns++)
#pragma unroll
                    for (int k = 0; k < 4; k++)
                        mma_f16_ss(tmem + ns * 128, ad + k * 2, bd + ns * 1024 + k * 2,
                                   IDESC, (uint32_t)(it | p | k));
            }
            TC_COMMIT(s0 + 8 + st * 8);
        }
    };

    ldg_chunk(0);
    sts_chunk(0);
    if (nk > 1) ldg_chunk(1);
    __syncthreads();
    mma_chunk(0, 0);

    int ph[2] = {0, 0};
#pragma unroll 2
    for (int it = 1; it < nk; it++) {
        const int st = it & 1;
        if (it >= 2) { mb_wait(s0 + 8 + st * 8, ph[st]); ph[st] ^= 1; }
        sts_chunk(st);
        if (it + 1 < nk) ldg_chunk(it + 1);
        __syncthreads();
        mma_chunk(it, st);
    }
    const int stl = (nk - 1) & 1;
    mb_wait(s0 + 8 + stl * 8, ph[stl]);
    TC_FENCE_AFTER();
    __syncthreads();

    // epilogue: warp w -> rows (w&3)*32, col half (w>>2)
    {
        float* ep = reinterpret_cast<float*>(smt + (size_t)w * 32 * 33 * 4);
        const int sp = w & 3;
        const int c_beg = (w >> 2) * (NT / 2);
        for (int c0 = c_beg; c0 < c_beg + NT / 2; c0 += 32) {
            uint32_t r[32];
            ldtm32(r, tmem + c0);
            TC_WAIT_LD();
#pragma unroll
            for (int j = 0; j < 32; j++) ep[lane * 33 + j] = __uint_as_float(r[j]);
            __syncwarp();
            const float bv = bias[n0 + c0 + lane];
#pragma unroll
            for (int rr = 0; rr < 32; rr++) {
                float x = fmaxf(ep[rr * 33 + lane] + bv, 0.f);
                __nv_bfloat16 h, l; split2(x, h, l);
                size_t o = (size_t)(m0 + sp * 32 + rr) * ldc + n0 + c0 + lane;
                Chi[o] = h; Clo[o] = l;
            }
            __syncwarp();
        }
    }
    __syncthreads();
    if (w == 0) { TC_RELINQ(); TC_DEALLOC(tmem, 512); }
#else
    // ================= HMMA fallback (cp.async, unchanged) =================
    constexpr int NW = NT / 4;
    constexpr int N8 = NW / 8;
    const int wm = (w & 1) * 64;
    const int wn = (w >> 1) * NW;

    float acc[4][N8][4];
#pragma unroll
    for (int i = 0; i < 4; i++)
#pragma unroll
        for (int j = 0; j < N8; j++)
#pragma unroll
            for (int r = 0; r < 4; r++) acc[i][j][r] = 0.f;

    load_chunk_ca<NT>(s_tile, Ahi, Alo, Bhi, Blo, m0, n0, K, 0, tid);
    cp_commit();
    if (nk > 1) {
        load_chunk_ca<NT>(s_tile + STG, Ahi, Alo, Bhi, Blo, m0, n0, K, 64, tid);
        cp_commit();
    }

    for (int it = 0; it < nk; it++) {
        const int st = it & 1;
        if (it + 1 < nk) cp_wait1(); else cp_wait0();
        __syncthreads();
        const uint32_t sb = s_tile + st * STG;
#pragma unroll
        for (int kk = 0; kk < 4; kk++) {
            const uint32_t kb = kk * 32 + ((lane >> 4) * 16);
            uint32_t ah[4][4], al[4][4], bh[N8][2], bl[N8][2];
#pragma unroll
            for (int mi = 0; mi < 4; mi++) {
                uint32_t off = (uint32_t)((wm + mi * 16 + (lane & 15)) * 128) + kb;
                uint32_t sw = off ^ ((off >> 3) & 0x70u);
                ldsm4(ah[mi], sb + sw);
                ldsm4(al[mi], sb + 16384 + sw);
            }
#pragma unroll
            for (int nt = 0; nt < N8 / 2; nt++) {
                uint32_t off = (uint32_t)((wn + nt * 16 + (lane & 15)) * 128) + kb;
                uint32_t sw = off ^ ((off >> 3) & 0x70u);
                uint32_t t[4];
                ldsm4(t, sb + 32768 + sw);
                bh[nt * 2][0] = t[0]; bh[nt * 2][1] = t[2];
                bh[nt * 2 + 1][0] = t[1]; bh[nt * 2 + 1][1] = t[3];
                ldsm4(t, sb + 32768 + NT * 128u + sw);
                bl[nt * 2][0] = t[0]; bl[nt * 2][1] = t[2];
                bl[nt * 2 + 1][0] = t[1]; bl[nt * 2 + 1][1] = t[3];
            }
#pragma unroll
            for (int mi = 0; mi < 4; mi++)
#pragma unroll
                for (int j = 0; j < N8; j++) {
                    mma16816(acc[mi][j], ah[mi], bh[j]);
                    mma16816(acc[mi][j], al[mi], bh[j]);
                    mma16816(acc[mi][j], ah[mi], bl[j]);
                }
        }
        __syncthreads();
        if (it + 2 < nk) {
            load_chunk_ca<NT>(s_tile + st * STG, Ahi, Alo, Bhi, Blo, m0, n0, K, (it + 2) << 6, tid);
            cp_commit();
        }
    }

#pragma unroll
    for (int j = 0; j < N8; j++) {
        int c0 = n0 + wn + j * 8 + (lane & 3) * 2;
        float2 b2 = *reinterpret_cast<const float2*>(bias + c0);
#pragma unroll
        for (int mi = 0; mi < 4; mi++) {
            int r0 = m0 + wm + mi * 16 + (lane >> 2);
#pragma unroll
            for (int hrow = 0; hrow < 2; hrow++) {
                int r = r0 + hrow * 8;
                float x0 = fmaxf(acc[mi][j][hrow * 2 + 0] + b2.x, 0.f);
                float x1 = fmaxf(acc[mi][j][hrow * 2 + 1] + b2.y, 0.f);
                __nv_bfloat162 h2, l2;
                split2(x0, h2.x, l2.x);
                split2(x1, h2.y, l2.y);
                size_t o = (size_t)r * ldc + c0;
                *reinterpret_cast<__nv_bfloat162*>(Chi + o) = h2;
                *reinterpret_cast<__nv_bfloat162*>(Clo + o) = l2;
            }
        }
    }
#endif
}

// ---------------------------------------------------------------------------
// One fused conversion kernel: dense -> p planes, all 7 weights -> wt planes.
// (Single launch so ncu -s 5 lands on a GEMM.)
// ---------------------------------------------------------------------------
__global__ __launch_bounds__(256) void conv_all(
    const float* __restrict__ dense,
    const float* __restrict__ bw0, const float* __restrict__ bw1, const float* __restrict__ bw2,
    const float* __restrict__ tw0, const float* __restrict__ tw1, const float* __restrict__ tw2,
    const float* __restrict__ tw3,
    __nv_bfloat16* __restrict__ pHi, __nv_bfloat16* __restrict__ pLo,
    __nv_bfloat16* __restrict__ wHi, __nv_bfloat16* __restrict__ wLo)
{
    size_t idx = (size_t)blockIdx.x * 256 + threadIdx.x;
    const size_t ND = (size_t)BATCH * 64;
    if (idx < ND) {
        int row = (int)(idx >> 6), c = (int)(idx & 63);
        float x = (c < 13) ? dense[(size_t)row * 13 + c] : 0.f;
        split2(x, pHi[idx], pLo[idx]);
        return;
    }
    size_t wv = idx - ND;
    if (wv >= 2424832) return;
    const float* src; int K, N, ksh; size_t off;
    if      (wv < 32768)   { src = bw0; K = 13;   N = 512;  ksh = 6;  off = 0; }
    else if (wv < 163840)  { src = bw1; K = 512;  N = 256;  ksh = 9;  off = 32768; }
    else if (wv < 196608)  { src = bw2; K = 256;  N = 128;  ksh = 8;  off = 163840; }
    else if (wv < 720896)  { src = tw0; K = 506;  N = 1024; ksh = 9;  off = 196608; }
    else if (wv < 1769472) { src = tw1; K = 1024; N = 1024; ksh = 10; off = 720896; }
    else if (wv < 2293760) { src = tw2; K = 1024; N = 512;  ksh = 10; off = 1769472; }
    else                   { src = tw3; K = 512;  N = 256;  ksh = 9;  off = 2293760; }
    size_t l = wv - off;
    int n = (int)(l >> ksh), k = (int)(l & ((1u << ksh) - 1));
    float x = (k < K) ? src[(size_t)k * N + n] : 0.f;
    split2(x, wHi[wv], wLo[wv]);
}

// ---------------------------------------------------------------------------
__global__ __launch_bounds__(64) void interact2(
    const __nv_bfloat16* __restrict__ hhi, const __nv_bfloat16* __restrict__ hlo,
    const int* __restrict__ sidx, const float* __restrict__ emb,
    __nv_bfloat16* __restrict__ ohi, __nv_bfloat16* __restrict__ olo)
{
    __shared__ float comb[2][28][129];
    const int t = threadIdx.x;

    for (int idx = t; idx < 2 * 28 * 128; idx += 64) {
        int s = idx / (28 * 128);
        int rem = idx - s * 28 * 128;
        int j = rem >> 7, d = rem & 127;
        size_t row = (size_t)blockIdx.x * 2 + s;
        float v;
        if (j == 0)
            v = __bfloat162float(hhi[row * 128 + d]) + __bfloat162float(hlo[row * 128 + d]);
        else if (j <= 26) {
            unsigned e = ((unsigned)sidx[row * 26 + (j - 1)]) & VOCAB_MASK;
            v = emb[(size_t)e * 128 + d];
        } else v = 0.f;
        comb[s][j][d] = v;
    }
    __syncthreads();

    const int s = t >> 5, lane = t & 31;
    const size_t row = (size_t)blockIdx.x * 2 + s;
    __nv_bfloat16* oh = ohi + row * 512;
    __nv_bfloat16* ol = olo + row * 512;

    for (int d = lane; d < 128; d += 32) {
        oh[d] = hhi[row * 128 + d];
        ol[d] = hlo[row * 128 + d];
    }
    if (lane < 6) {
        oh[506 + lane] = __float2bfloat16(0.f);
        ol[506 + lane] = __float2bfloat16(0.f);
    }

    if (lane < 28) {
        int ty = 0, rem = lane;
        while (rem >= 7 - ty) { rem -= 7 - ty; ty++; }
        int tx = ty + rem;
        int i0 = ty * 4, j0 = tx * 4;

        float a4[4], b4[4], acc[4][4];
#pragma unroll
        for (int a = 0; a < 4; a++)
#pragma unroll
            for (int b = 0; b < 4; b++) acc[a][b] = 0.f;

#pragma unroll 4
        for (int d = 0; d < 128; d++) {
#pragma unroll
            for (int a = 0; a < 4; a++) a4[a] = comb[s][i0 + a][d];
#pragma unroll
            for (int b = 0; b < 4; b++) b4[b] = comb[s][j0 + b][d];
#pragma unroll
            for (int a = 0; a < 4; a++)
#pragma unroll
                for (int b = 0; b < 4; b++)
                    acc[a][b] = fmaf(a4[a], b4[b], acc[a][b]);
        }
#pragma unroll
        for (int a = 0; a < 4; a++) {
            int i = i0 + a;
#pragma unroll
            for (int b = 0; b < 4; b++) {
                int j = j0 + b;
                if (j >= i && i < 27 && j < 27) {
                    int p = 27 * i - (i * (i - 1)) / 2 + (j - i);
                    __nv_bfloat16 h, l;
                    split2(acc[a][b], h, l);
                    oh[128 + p] = h;
                    ol[128 + p] = l;
                }
            }
        }
    }
}

// ---------------------------------------------------------------------------
__global__ __launch_bounds__(256) void final_k(
    const __nv_bfloat16* __restrict__ Ahi, const __nv_bfloat16* __restrict__ Alo,
    const float* __restrict__ w, const float* __restrict__ bias, float* __restrict__ out)
{
    int warp = (blockIdx.x * blockDim.x + threadIdx.x) >> 5;
    int lane = threadIdx.x & 31;
    const __nv_bfloat16* ah = Ahi + (size_t)warp * 256;
    const __nv_bfloat16* al = Alo + (size_t)warp * 256;
    float s = 0.f;
#pragma unroll
    for (int i = 0; i < 8; i++) {
        int c = lane + i * 32;
        float a = __bfloat162float(ah[c]) + __bfloat162float(al[c]);
        s = fmaf(a, __ldg(&w[c]), s);
    }
#pragma unroll
    for (int o = 16; o; o >>= 1) s += __shfl_xor_sync(0xFFFFFFFFu, s, o);
    if (lane == 0) out[warp] = s + bias[0];
}

// ---------------------------------------------------------------------------
extern "C" void kernel_launch(void* const* d_in, const int* in_sizes, int n_in,
                              void* d_out, int out_size)
{
    const float* dense = (const float*)d_in[0];
    const int*   sidx  = (const int*)d_in[1];
    const float* emb   = (const float*)d_in[2];
    const float* bw0 = (const float*)d_in[3];  const float* bb0 = (const float*)d_in[4];
    const float* bw1 = (const float*)d_in[5];  const float* bb1 = (const float*)d_in[6];
    const float* bw2 = (const float*)d_in[7];  const float* bb2 = (const float*)d_in[8];
    const float* tw0 = (const float*)d_in[9];  const float* tb0 = (const float*)d_in[10];
    const float* tw1 = (const float*)d_in[11]; const float* tb1 = (const float*)d_in[12];
    const float* tw2 = (const float*)d_in[13]; const float* tb2 = (const float*)d_in[14];
    const float* tw3 = (const float*)d_in[15]; const float* tb3 = (const float*)d_in[16];
    const float* tw4 = (const float*)d_in[17]; const float* tb4 = (const float*)d_in[18];
    float* out = (float*)d_out;

    __nv_bfloat16 *pHi, *pLo, *qHi, *qLo, *hHi, *hLo, *wtHi, *wtLo;
    cudaGetSymbolAddress((void**)&pHi, g_p_hi);
    cudaGetSymbolAddress((void**)&pLo, g_p_lo);
    cudaGetSymbolAddress((void**)&qHi, g_q_hi);
    cudaGetSymbolAddress((void**)&qLo, g_q_lo);
    cudaGetSymbolAddress((void**)&hHi, g_h_hi);
    cudaGetSymbolAddress((void**)&hLo, g_h_lo);
    cudaGetSymbolAddress((void**)&wtHi, g_wt_hi);
    cudaGetSymbolAddress((void**)&wtLo, g_wt_lo);

    const int SM256 = 2048 + 2 * (32768 + 2 * 256 * 128);  // 198656
    const int SM128 = 2048 + 2 * (32768 + 2 * 128 * 128);  // 133120
    cudaFuncSetAttribute(gemm_tc<256, 64>,   cudaFuncAttributeMaxDynamicSharedMemorySize, SM256);
    cudaFuncSetAttribute(gemm_tc<256, 512>,  cudaFuncAttributeMaxDynamicSharedMemorySize, SM256);
    cudaFuncSetAttribute(gemm_tc<256, 1024>, cudaFuncAttributeMaxDynamicSharedMemorySize, SM256);
    cudaFuncSetAttribute(gemm_tc<128, 256>,  cudaFuncAttributeMaxDynamicSharedMemorySize, SM128);

    // transposed weight plane offsets ([N, Kpad])
    const size_t o0 = 0;                    // 512 x 64
    const size_t o1 = o0 + 512 * 64;        // 256 x 512
    const size_t o2 = o1 + 256 * 512;       // 128 x 256
    const size_t o3 = o2 + 128 * 256;       // 1024 x 512
    const size_t o4 = o3 + 1024 * 512;      // 1024 x 1024
    const size_t o5 = o4 + 1024 * 1024;     // 512 x 1024
    const size_t o6 = o5 + 512 * 1024;      // 256 x 512

    // launch 0: all conversions fused
    conv_all<<<25856, 256>>>(dense, bw0, bw1, bw2, tw0, tw1, tw2, tw3,
                             pHi, pLo, wtHi, wtLo);

    // bottom MLP (launches 1-3)
    gemm_tc<256, 64><<<dim3(2, 512), 256, SM256>>>(
        pHi, pLo, wtHi + o0, wtLo + o0, bb0, qHi, qLo, 512);
    gemm_tc<256, 512><<<dim3(1, 512), 256, SM256>>>(
        qHi, qLo, wtHi + o1, wtLo + o1, bb1, pHi, pLo, 256);
    gemm_tc<128, 256><<<dim3(1, 512), 256, SM128>>>(
        pHi, pLo, wtHi + o2, wtLo + o2, bb2, hHi, hLo, 128);

    // launch 4: gather + interaction -> q planes (stride 512)
    interact2<<<BATCH / 2, 64>>>(hHi, hLo, sidx, emb, qHi, qLo);

    // top MLP (launches 5-8) — launch 5 (tw0) is the ncu-profiled one
    gemm_tc<256, 512><<<dim3(4, 512), 256, SM256>>>(
        qHi, qLo, wtHi + o3, wtLo + o3, tb0, pHi, pLo, 1024);
    gemm_tc<256, 1024><<<dim3(4, 512), 256, SM256>>>(
        pHi, pLo, wtHi + o4, wtLo + o4, tb1, qHi, qLo, 1024);
    gemm_tc<256, 1024><<<dim3(2, 512), 256, SM256>>>(
        qHi, qLo, wtHi + o5, wtLo + o5, tb2, pHi, pLo, 512);
    gemm_tc<256, 512><<<dim3(1, 512), 256, SM256>>>(
        pHi, pLo, wtHi + o6, wtLo + o6, tb3, qHi, qLo, 256);

    // launch 9: final 256 -> 1
    final_k<<<BATCH * 32 / 256, 256>>>(qHi, qLo, tw4, tb4, out);
}